// round 11
// baseline (speedup 1.0000x reference)
#include <cuda_runtime.h>
#include <math.h>
#include <stdint.h>

#define NH 8
#define CDIM 512
#define HW 256
#define CH 64
#define BATCH 4
#define TCACHE 63
#define SK 72
#define NKV 4
#define ITERS 64
#define KEYTOT 16384          // 64 * 256
#define LOG2E 1.4426950408889634f

__device__ float g_wqkv_n[3 * CDIM * CDIM];   // normalized, tf32, pc8-permuted on k
__device__ float g_wproj_n[CDIM * CDIM];      // normalized, tf32, pc8-permuted on k
__device__ float g_xt[BATCH * HW * CDIM];     // x^T tf32 permuted
__device__ float g_ot[BATCH * HW * CDIM];     // o^T tf32 permuted
__device__ float2 g_rope[64 * 32];
__device__ float g_q[BATCH * NH * HW * CH];
__device__ float g_k[BATCH * NH * HW * CH];
__device__ float g_v[BATCH * NH * HW * CH];
__device__ float g_kp[BATCH * NH * KEYTOT * CH];   // pre-roped K, tf32, ch-permuted
__device__ float g_vtg[BATCH * NH * CH * KEYTOT];  // V^T, tf32, key-permuted in 8-groups
__device__ float g_o[BATCH * CDIM * HW];
__device__ float g_po[BATCH * NH * 2 * NKV * 64 * 128];
__device__ float g_pl[BATCH * NH * 2 * NKV * 128];

__device__ __forceinline__ unsigned f2tf(float x) {
    unsigned r;
    asm("cvt.rna.tf32.f32 %0, %1;" : "=r"(r) : "f"(x));
    return r;
}
__device__ __forceinline__ float ex2(float x) {
    float y;
    asm("ex2.approx.f32 %0, %1;" : "=f"(y) : "f"(x));
    return y;
}
__device__ __forceinline__ void mma8(float c[4], const unsigned a[4], unsigned b0, unsigned b1) {
    asm volatile(
        "mma.sync.aligned.m16n8k8.row.col.f32.tf32.tf32.f32 "
        "{%0,%1,%2,%3}, {%4,%5,%6,%7}, {%8,%9}, {%0,%1,%2,%3};\n"
        : "+f"(c[0]), "+f"(c[1]), "+f"(c[2]), "+f"(c[3])
        : "r"(a[0]), "r"(a[1]), "r"(a[2]), "r"(a[3]), "r"(b0), "r"(b1));
}
__device__ __forceinline__ int pc8(int r) { return ((r & 3) << 1) | (r >> 2); }

__device__ __forceinline__ void cpa16(uint32_t dst, const void* src) {
    asm volatile("cp.async.cg.shared.global [%0], [%1], 16;" :: "r"(dst), "l"(src));
}
#define CP_COMMIT() asm volatile("cp.async.commit_group;")
#define CP_WAIT1()  asm volatile("cp.async.wait_group 1;")
#define CP_WAIT0()  asm volatile("cp.async.wait_group 0;")

// ---------------- K1a: mp_weight normalization + tf32/permute ----------------
__global__ void norm_kernel(const float* __restrict__ wq, const float* __restrict__ wp) {
    int r = blockIdx.x;
    bool is_q = (r < 3 * CDIM);
    const float* src = is_q ? wq + (size_t)r * CDIM : wp + (size_t)(r - 3 * CDIM) * CDIM;
    float* dst = is_q ? g_wqkv_n + (size_t)r * CDIM : g_wproj_n + (size_t)(r - 3 * CDIM) * CDIM;

    float4 v = reinterpret_cast<const float4*>(src)[threadIdx.x];
    float ss = v.x * v.x + v.y * v.y + v.z * v.z + v.w * v.w;
    for (int o = 16; o; o >>= 1) ss += __shfl_xor_sync(0xffffffffu, ss, o);
    __shared__ float wsum[4];
    if ((threadIdx.x & 31) == 0) wsum[threadIdx.x >> 5] = ss;
    __syncthreads();
    float nrm = sqrtf(wsum[0] + wsum[1] + wsum[2] + wsum[3]);
    float s512 = sqrtf((float)CDIM);
    float scale = 1.0f / ((1e-4f + nrm / s512) * s512);
    float o4[4] = {v.x * scale, v.y * scale, v.z * scale, v.w * scale};
    int c0 = threadIdx.x * 4;
#pragma unroll
    for (int j = 0; j < 4; j++) {
        int c = c0 + j;
        dst[(c & ~7) | pc8(c & 7)] = __uint_as_float(f2tf(o4[j]));
    }
}

// ---------------- K1b: rope table ----------------
__global__ void rope_table_kernel() {
    int idx = blockIdx.x * blockDim.x + threadIdx.x;
    if (idx < 64 * 32) {
        int t = idx >> 5, j = idx & 31;
        float inv = powf(10000.0f, -(2.0f * (float)j) / 64.0f);
        float a = (float)t * inv;
        g_rope[idx] = make_float2(cosf(a), sinf(a));
    }
}

// ---------------- K1c: generic 512x256 transpose -> [b][s][k_phys] tf32 ----------------
__global__ void tr_kernel(const float* __restrict__ src, float* __restrict__ dst) {
    __shared__ float t[32][33];
    int bb = blockIdx.z;
    int k0 = blockIdx.x * 32, s0 = blockIdx.y * 32;
    int tx = threadIdx.x, ty = threadIdx.y;
#pragma unroll
    for (int j = 0; j < 4; j++)
        t[ty + j * 8][tx] = src[((size_t)bb * CDIM + (k0 + ty + j * 8)) * HW + s0 + tx];
    __syncthreads();
    int kp = k0 + ((tx & ~7) | pc8(tx & 7));
#pragma unroll
    for (int j = 0; j < 4; j++)
        dst[((size_t)bb * HW + s0 + ty + j * 8) * CDIM + kp] =
            __uint_as_float(f2tf(t[tx][ty + j * 8]));
}

// ---------------- K2: QKV GEMM (tf32 mma) -> q/k/v [b][head][s][ch] ----------------
#define QS 20
__global__ __launch_bounds__(128) void qkv_gemm_kernel() {
    __shared__ float As[2][64 * QS];
    __shared__ float Bs[2][64 * QS];
    int sblk = blockIdx.x, oblk = blockIdx.y, bb = blockIdx.z;
    int tid = threadIdx.x;
    int w = tid >> 5, l = tid & 31;
    int la = l >> 2, lb = l & 3;

    const float* xa = g_xt + ((size_t)bb * HW + sblk * 64) * CDIM;
    const float* wb = g_wqkv_n + (size_t)oblk * 64 * CDIM;

    int row = tid >> 1, half = tid & 1;
    uint32_t as_u[2] = {(uint32_t)__cvta_generic_to_shared(As[0]),
                        (uint32_t)__cvta_generic_to_shared(As[1])};
    uint32_t bs_u[2] = {(uint32_t)__cvta_generic_to_shared(Bs[0]),
                        (uint32_t)__cvta_generic_to_shared(Bs[1])};

    auto load_stage = [&](int kc) {
        int st = kc & 1;
        uint32_t ad = as_u[st] + (uint32_t)(row * QS + half * 8) * 4u;
        uint32_t bd = bs_u[st] + (uint32_t)(row * QS + half * 8) * 4u;
        const float* asrc = xa + (size_t)row * CDIM + kc * 16 + half * 8;
        const float* bsrc = wb + (size_t)row * CDIM + kc * 16 + half * 8;
        cpa16(ad, asrc); cpa16(ad + 16, asrc + 4);
        cpa16(bd, bsrc); cpa16(bd + 16, bsrc + 4);
    };

    float acc[8][4] = {};
    load_stage(0); CP_COMMIT();

    for (int kc = 0; kc < 32; kc++) {
        if (kc + 1 < 32) { load_stage(kc + 1); CP_COMMIT(); CP_WAIT1(); }
        else CP_WAIT0();
        __syncthreads();
        const float* Ab = As[kc & 1];
        const float* Bb = Bs[kc & 1];
#pragma unroll
        for (int c2 = 0; c2 < 2; c2++) {
            uint2 a0 = *reinterpret_cast<const uint2*>(&Ab[(w * 16 + la) * QS + c2 * 8 + 2 * lb]);
            uint2 a1 = *reinterpret_cast<const uint2*>(&Ab[(w * 16 + la + 8) * QS + c2 * 8 + 2 * lb]);
            unsigned A[4] = {a0.x, a1.x, a0.y, a1.y};
#pragma unroll
            for (int nn = 0; nn < 8; nn++) {
                uint2 b = *reinterpret_cast<const uint2*>(&Bb[(nn * 8 + la) * QS + c2 * 8 + 2 * lb]);
                mma8(acc[nn], A, b.x, b.y);
            }
        }
        __syncthreads();
    }

    int which = oblk >> 3;
    int head = oblk & 7;
    float* dst = ((which == 0) ? g_q : (which == 1) ? g_k : g_v) +
                 (size_t)(bb * NH + head) * HW * CH;
    int srow = sblk * 64 + w * 16 + la;
#pragma unroll
    for (int nn = 0; nn < 8; nn++) {
        int ch = nn * 8 + 2 * lb;
        *reinterpret_cast<float2*>(&dst[(size_t)srow * CH + ch]) =
            make_float2(acc[nn][0], acc[nn][1]);
        *reinterpret_cast<float2*>(&dst[(size_t)(srow + 8) * CH + ch]) =
            make_float2(acc[nn][2], acc[nn][3]);
    }
}

// ---------------- K2b: K prepass — rope + tf32 + ch-permute -> g_kp ----------------
__global__ void rope_k_kernel(const float* __restrict__ ck) {
    int t = blockIdx.x, bhi = blockIdx.y, row = threadIdx.x;  // 256 threads
    const float* src = (t < TCACHE)
        ? ck + ((((size_t)bhi * TCACHE + t) * HW) + row) * CH
        : g_k + (((size_t)bhi * HW) + row) * CH;
    unsigned* dst = reinterpret_cast<unsigned*>(
        g_kp + (((size_t)bhi * KEYTOT) + t * HW + row) * CH);
    const float2* tq = g_rope + t * 32;
#pragma unroll
    for (int g = 0; g < 8; g++) {
        float4 x0 = *reinterpret_cast<const float4*>(src + 8 * g);
        float4 x1 = *reinterpret_cast<const float4*>(src + 8 * g + 4);
        float2 t0 = tq[4 * g], t1 = tq[4 * g + 1], t2 = tq[4 * g + 2], t3 = tq[4 * g + 3];
        float l0 = x0.x * t0.x - x0.y * t0.y;
        float l1 = x0.x * t0.y + x0.y * t0.x;
        float l2 = x0.z * t1.x - x0.w * t1.y;
        float l3 = x0.z * t1.y + x0.w * t1.x;
        float l4 = x1.x * t2.x - x1.y * t2.y;
        float l5 = x1.x * t2.y + x1.y * t2.x;
        float l6 = x1.z * t3.x - x1.w * t3.y;
        float l7 = x1.z * t3.y + x1.w * t3.x;
        dst[8 * g + 0] = f2tf(l0); dst[8 * g + 1] = f2tf(l4);
        dst[8 * g + 2] = f2tf(l1); dst[8 * g + 3] = f2tf(l5);
        dst[8 * g + 4] = f2tf(l2); dst[8 * g + 5] = f2tf(l6);
        dst[8 * g + 6] = f2tf(l3); dst[8 * g + 7] = f2tf(l7);
    }
}

// ---------------- K2c: V prepass — transpose + tf32 + key-permute -> g_vtg ----------------
__global__ void vt_kernel(const float* __restrict__ cv) {
    __shared__ float tl[32][33];
    int tile = blockIdx.x;          // 16: (ch half, key oct)
    int t = blockIdx.y, bhi = blockIdx.z;
    int ch0 = (tile & 1) * 32, key0 = (tile >> 1) * 32;
    int tx = threadIdx.x, ty = threadIdx.y;
    const float* src = (t < TCACHE)
        ? cv + (((size_t)bhi * TCACHE + t) * HW) * CH
        : g_v + ((size_t)bhi * HW) * CH;
#pragma unroll
    for (int j = 0; j < 4; j++)
        tl[ty + j * 8][tx] = src[(size_t)(key0 + ty + j * 8) * CH + ch0 + tx];
    __syncthreads();
    int keyp = key0 + ((tx & ~7) | pc8(tx & 7));
#pragma unroll
    for (int j = 0; j < 4; j++)
        g_vtg[((size_t)bhi * CH + ch0 + ty + j * 8) * KEYTOT + t * HW + keyp] =
            __uint_as_float(f2tf(tl[tx][ty + j * 8]));
}

// ---------------- K3: flash attention v7 — no in-loop conversion, 3-stage, 1 barrier ----------------
__global__ __launch_bounds__(128, 2) void attn_kernel() {
    extern __shared__ float smf[];
    // stages: K at s*64*SK (s=0..2), V^T at (3+s)*64*SK
    int qp = blockIdx.x >> 2, kvq = blockIdx.x & 3;
    int head = blockIdx.y, bb = blockIdx.z;
    int bhi = bb * NH + head;
    int tid = threadIdx.x;
    int w = tid >> 5, l = tid & 31;
    int la = l >> 2, lb = l & 3;

    uint32_t sm_u = (uint32_t)__cvta_generic_to_shared(smf);

    int krow = tid >> 1, half = tid & 1;
    int krow_p = (krow & ~7) | pc8(krow & 7);

    const float* kbase = g_kp + (size_t)bhi * KEYTOT * CH + (size_t)kvq * ITERS * 64 * CH;
    const float* vbase = g_vtg + (size_t)bhi * CH * KEYTOT + (size_t)kvq * ITERS * 64;

    auto issue = [&](int i) {
        int s = i % 3;
        // K tile i: rows permuted at dst
        uint32_t kd = sm_u + (uint32_t)(s * 64 * SK + krow_p * SK + half * 32) * 4u;
        const float* ks = kbase + (size_t)(i * 64 + krow) * CH + half * 32;
#pragma unroll
        for (int c = 0; c < 8; c++) cpa16(kd + c * 16, ks + c * 4);
        // V^T tile i: row = ch, 64 keys contiguous
        uint32_t vd = sm_u + (uint32_t)((3 + s) * 64 * SK + krow * SK + half * 32) * 4u;
        const float* vs = vbase + (size_t)krow * KEYTOT + i * 64 + half * 32;
#pragma unroll
        for (int c = 0; c < 8; c++) cpa16(vd + c * 16, vs + c * 4);
    };

    // ---- prologue: stage Q (rope 63, * log2e/8, tf32, permuted) in smem, load frags ----
    {
        int r = tid;
        const float* qpv = g_q + (((size_t)bhi) * HW + qp * 128 + r) * CH;
        const float2* tq = g_rope + 63 * 32;
        const float sc = 0.125f * LOG2E;
        unsigned* pr = reinterpret_cast<unsigned*>(smf + r * SK);
#pragma unroll
        for (int g = 0; g < 8; g++) {
            float4 x0 = *reinterpret_cast<const float4*>(qpv + 8 * g);
            float4 x1 = *reinterpret_cast<const float4*>(qpv + 8 * g + 4);
            float2 t0 = tq[4 * g], t1 = tq[4 * g + 1], t2 = tq[4 * g + 2], t3 = tq[4 * g + 3];
            float l0 = (x0.x * t0.x - x0.y * t0.y) * sc;
            float l1 = (x0.x * t0.y + x0.y * t0.x) * sc;
            float l2 = (x0.z * t1.x - x0.w * t1.y) * sc;
            float l3 = (x0.z * t1.y + x0.w * t1.x) * sc;
            float l4 = (x1.x * t2.x - x1.y * t2.y) * sc;
            float l5 = (x1.x * t2.y + x1.y * t2.x) * sc;
            float l6 = (x1.z * t3.x - x1.w * t3.y) * sc;
            float l7 = (x1.z * t3.y + x1.w * t3.x) * sc;
            pr[8 * g + 0] = f2tf(l0); pr[8 * g + 1] = f2tf(l4);
            pr[8 * g + 2] = f2tf(l1); pr[8 * g + 3] = f2tf(l5);
            pr[8 * g + 4] = f2tf(l2); pr[8 * g + 5] = f2tf(l6);
            pr[8 * g + 6] = f2tf(l3); pr[8 * g + 7] = f2tf(l7);
        }
    }
    __syncthreads();

    unsigned qa[2][8][4];
#pragma unroll
    for (int tt = 0; tt < 2; tt++) {
        int r0 = tt * 64 + 16 * w + la;
#pragma unroll
        for (int kk = 0; kk < 8; kk++) {
            uint2 p0 = *reinterpret_cast<const uint2*>(&smf[r0 * SK + kk * 8 + 2 * lb]);
            uint2 p1 = *reinterpret_cast<const uint2*>(&smf[(r0 + 8) * SK + kk * 8 + 2 * lb]);
            qa[tt][kk][0] = p0.x; qa[tt][kk][1] = p1.x; qa[tt][kk][2] = p0.y; qa[tt][kk][3] = p1.y;
        }
    }
    __syncthreads();

    issue(0); CP_COMMIT();
    issue(1); CP_COMMIT();

    float oacc[2][8][4] = {};
    float ls[2][2] = {};

    for (int i = 0; i < ITERS; i++) {
        CP_WAIT1();        // group i complete
        __syncthreads();   // cross-thread visibility + stage (i+2)%3 reads sealed
        if (i + 2 < ITERS) issue(i + 2);
        CP_COMMIT();       // unconditional: keeps group numbering aligned

        const float* Kb = smf + (i % 3) * 64 * SK;
        const float* Vb = smf + (3 + i % 3) * 64 * SK;

        // ---- S = QK^T (hoisted K frags), P = exp2 into pa ----
        unsigned pa[2][8][4];
        float s00 = 0.f, s01 = 0.f, s10 = 0.f, s11 = 0.f;
#pragma unroll
        for (int nn = 0; nn < 8; nn++) {
            const float* kr = Kb + (nn * 8 + la) * SK;
            uint2 bf[8];
#pragma unroll
            for (int kk = 0; kk < 8; kk++)
                bf[kk] = *reinterpret_cast<const uint2*>(kr + kk * 8 + 2 * lb);
#pragma unroll
            for (int tt = 0; tt < 2; tt++) {
                float c[4] = {0.f, 0.f, 0.f, 0.f};
#pragma unroll
                for (int kk = 0; kk < 8; kk++) mma8(c, qa[tt][kk], bf[kk].x, bf[kk].y);
                float p0 = ex2(c[0]);
                float p1 = ex2(c[1]);
                float p2 = ex2(c[2]);
                float p3 = ex2(c[3]);
                if (tt == 0) { s00 += p0 + p1; s01 += p2 + p3; }
                else         { s10 += p0 + p1; s11 += p2 + p3; }
                pa[tt][nn][0] = __float_as_uint(p0);
                pa[tt][nn][1] = __float_as_uint(p2);
                pa[tt][nn][2] = __float_as_uint(p1);
                pa[tt][nn][3] = __float_as_uint(p3);
            }
        }
        s00 += __shfl_xor_sync(0xffffffffu, s00, 1);
        s00 += __shfl_xor_sync(0xffffffffu, s00, 2);
        s01 += __shfl_xor_sync(0xffffffffu, s01, 1);
        s01 += __shfl_xor_sync(0xffffffffu, s01, 2);
        s10 += __shfl_xor_sync(0xffffffffu, s10, 1);
        s10 += __shfl_xor_sync(0xffffffffu, s10, 2);
        s11 += __shfl_xor_sync(0xffffffffu, s11, 1);
        s11 += __shfl_xor_sync(0xffffffffu, s11, 2);
        ls[0][0] += s00; ls[0][1] += s01;
        ls[1][0] += s10; ls[1][1] += s11;

        // ---- O += P V ----
#pragma unroll
        for (int kk = 0; kk < 8; kk++) {
#pragma unroll
            for (int nn = 0; nn < 8; nn++) {
                uint2 b = *reinterpret_cast<const uint2*>(&Vb[(nn * 8 + la) * SK + kk * 8 + 2 * lb]);
                mma8(oacc[0][nn], pa[0][kk], b.x, b.y);
                mma8(oacc[1][nn], pa[1][kk], b.x, b.y);
            }
        }
    }

    // ---- epilogue ----
    int pbase = ((bhi * 2 + qp) * NKV + kvq);
    float* po = g_po + (size_t)pbase * 8192;
    int prow = 16 * w + la;
#pragma unroll
    for (int tt = 0; tt < 2; tt++) {
        int row = tt * 64 + prow;
#pragma unroll
        for (int nn = 0; nn < 8; nn++) {
            int ch = nn * 8 + 2 * lb;
            po[(ch + 0) * 128 + row]     = oacc[tt][nn][0];
            po[(ch + 1) * 128 + row]     = oacc[tt][nn][1];
            po[(ch + 0) * 128 + row + 8] = oacc[tt][nn][2];
            po[(ch + 1) * 128 + row + 8] = oacc[tt][nn][3];
        }
        if (lb == 0) {
            g_pl[pbase * 128 + row]     = ls[tt][0];
            g_pl[pbase * 128 + row + 8] = ls[tt][1];
        }
    }
}

// ---------------- K3b: split-KV combine -> g_o [oc][s] ----------------
__global__ __launch_bounds__(256) void combine_kernel() {
    int qp = blockIdx.x, head = blockIdx.y, bb = blockIdx.z;
    int pb = (((bb * NH + head) * 2 + qp) * NKV);
    int tid = threadIdx.x;
    __shared__ float il[128];
    if (tid < 128) {
        float den = 0.f;
#pragma unroll
        for (int k = 0; k < NKV; k++) den += g_pl[(pb + k) * 128 + tid];
        il[tid] = 1.0f / den;
    }
    __syncthreads();
    int ch = tid >> 2, sg = tid & 3;
    float* dst = g_o + ((size_t)bb * CDIM + (ch * NH + head)) * HW + qp * 128;
#pragma unroll 4
    for (int rr = 0; rr < 32; rr++) {
        int r = sg * 32 + rr;
        float acc = 0.f;
#pragma unroll
        for (int k = 0; k < NKV; k++)
            acc += g_po[(size_t)(pb + k) * 8192 + ch * 128 + r];
        dst[r] = acc * il[r];
    }
}

// ---------------- K4: proj GEMM (tf32 mma) + mp_sum ----------------
__global__ __launch_bounds__(128) void proj_kernel(const float* __restrict__ x,
                                                   float* __restrict__ out) {
    __shared__ float As[2][64 * QS];
    __shared__ float Bs[2][64 * QS];
    int sblk = blockIdx.x, oblk = blockIdx.y, bb = blockIdx.z;
    int tid = threadIdx.x;
    int w = tid >> 5, l = tid & 31;
    int la = l >> 2, lb = l & 3;

    const float* xa = g_ot + ((size_t)bb * HW + sblk * 64) * CDIM;
    const float* wb = g_wproj_n + (size_t)oblk * 64 * CDIM;

    int row = tid >> 1, half = tid & 1;
    uint32_t as_u[2] = {(uint32_t)__cvta_generic_to_shared(As[0]),
                        (uint32_t)__cvta_generic_to_shared(As[1])};
    uint32_t bs_u[2] = {(uint32_t)__cvta_generic_to_shared(Bs[0]),
                        (uint32_t)__cvta_generic_to_shared(Bs[1])};

    auto load_stage = [&](int kc) {
        int st = kc & 1;
        uint32_t ad = as_u[st] + (uint32_t)(row * QS + half * 8) * 4u;
        uint32_t bd = bs_u[st] + (uint32_t)(row * QS + half * 8) * 4u;
        const float* asrc = xa + (size_t)row * CDIM + kc * 16 + half * 8;
        const float* bsrc = wb + (size_t)row * CDIM + kc * 16 + half * 8;
        cpa16(ad, asrc); cpa16(ad + 16, asrc + 4);
        cpa16(bd, bsrc); cpa16(bd + 16, bsrc + 4);
    };

    float acc[8][4] = {};
    load_stage(0); CP_COMMIT();

    for (int kc = 0; kc < 32; kc++) {
        if (kc + 1 < 32) { load_stage(kc + 1); CP_COMMIT(); CP_WAIT1(); }
        else CP_WAIT0();
        __syncthreads();
        const float* Ab = As[kc & 1];
        const float* Bb = Bs[kc & 1];
#pragma unroll
        for (int c2 = 0; c2 < 2; c2++) {
            uint2 a0 = *reinterpret_cast<const uint2*>(&Ab[(w * 16 + la) * QS + c2 * 8 + 2 * lb]);
            uint2 a1 = *reinterpret_cast<const uint2*>(&Ab[(w * 16 + la + 8) * QS + c2 * 8 + 2 * lb]);
            unsigned A[4] = {a0.x, a1.x, a0.y, a1.y};
#pragma unroll
            for (int nn = 0; nn < 8; nn++) {
                uint2 b = *reinterpret_cast<const uint2*>(&Bb[(nn * 8 + la) * QS + c2 * 8 + 2 * lb]);
                mma8(acc[nn], A, b.x, b.y);
            }
        }
        __syncthreads();
    }

    const float norm = 1.3130643286f;  // 1/sqrt(0.7^2+0.3^2)
    int srow = sblk * 64 + w * 16 + la;
#pragma unroll
    for (int nn = 0; nn < 8; nn++) {
        int oc = oblk * 64 + nn * 8 + 2 * lb;
        size_t i00 = ((size_t)bb * CDIM + oc) * HW;
        size_t i01 = ((size_t)bb * CDIM + oc + 1) * HW;
        out[i00 + srow]     = (0.7f * x[i00 + srow]     + 0.3f * acc[nn][0]) * norm;
        out[i01 + srow]     = (0.7f * x[i01 + srow]     + 0.3f * acc[nn][1]) * norm;
        out[i00 + srow + 8] = (0.7f * x[i00 + srow + 8] + 0.3f * acc[nn][2]) * norm;
        out[i01 + srow + 8] = (0.7f * x[i01 + srow + 8] + 0.3f * acc[nn][3]) * norm;
    }
}

extern "C" void kernel_launch(void* const* d_in, const int* in_sizes, int n_in,
                              void* d_out, int out_size) {
    const float* x     = (const float*)d_in[0];
    const float* ck    = (const float*)d_in[1];
    const float* cv    = (const float*)d_in[2];
    const float* wqkv  = (const float*)d_in[3];
    const float* wproj = (const float*)d_in[4];
    float* out = (float*)d_out;

    norm_kernel<<<4 * CDIM, 128>>>(wqkv, wproj);
    rope_table_kernel<<<8, 256>>>();

    float* xt_sym; cudaGetSymbolAddress((void**)&xt_sym, g_xt);
    float* ot_sym; cudaGetSymbolAddress((void**)&ot_sym, g_ot);
    float* o_sym;  cudaGetSymbolAddress((void**)&o_sym,  g_o);

    tr_kernel<<<dim3(16, 8, 4), dim3(32, 8)>>>(x, xt_sym);
    qkv_gemm_kernel<<<dim3(4, 24, 4), 128>>>();

    rope_k_kernel<<<dim3(64, 32), 256>>>(ck);
    vt_kernel<<<dim3(16, 64, 32), dim3(32, 8)>>>(cv);

    int smem = 6 * 64 * SK * (int)sizeof(float);  // 110592 B -> 2 CTAs/SM
    cudaFuncSetAttribute(attn_kernel, cudaFuncAttributeMaxDynamicSharedMemorySize, smem);
    attn_kernel<<<dim3(8, NH, 4), 128, smem>>>();

    combine_kernel<<<dim3(2, NH, BATCH), 256>>>();
    tr_kernel<<<dim3(16, 8, 4), dim3(32, 8)>>>(o_sym, ot_sym);
    proj_kernel<<<dim3(4, 8, 4), 128>>>(x, out);
}

// round 12
// speedup vs baseline: 1.4295x; 1.4295x over previous
#include <cuda_runtime.h>
#include <math.h>
#include <stdint.h>

#define NH 8
#define CDIM 512
#define HW 256
#define CH 64
#define BATCH 4
#define TCACHE 63
#define SK 72
#define NKV 4
#define ITERS 64
#define LOG2E 1.4426950408889634f

__device__ float g_wqkv_n[3 * CDIM * CDIM];   // normalized, tf32, pc8-permuted on k
__device__ float g_wproj_n[CDIM * CDIM];      // normalized, tf32, pc8-permuted on k
__device__ float g_xt[BATCH * HW * CDIM];     // x^T tf32 permuted
__device__ float g_ot[BATCH * HW * CDIM];     // o^T tf32 permuted
__device__ float2 g_rope[64 * 32];
__device__ float g_q[BATCH * NH * HW * CH];
__device__ float g_k[BATCH * NH * HW * CH];
__device__ float g_v[BATCH * NH * HW * CH];
__device__ float g_o[BATCH * CDIM * HW];
__device__ float g_po[BATCH * NH * 2 * NKV * 64 * 128];
__device__ float g_pl[BATCH * NH * 2 * NKV * 128];

__device__ __forceinline__ unsigned f2tf(float x) {
    unsigned r;
    asm("cvt.rna.tf32.f32 %0, %1;" : "=r"(r) : "f"(x));
    return r;
}
__device__ __forceinline__ float ex2(float x) {
    float y;
    asm("ex2.approx.f32 %0, %1;" : "=f"(y) : "f"(x));
    return y;
}
__device__ __forceinline__ void mma8(float c[4], const unsigned a[4], unsigned b0, unsigned b1) {
    asm volatile(
        "mma.sync.aligned.m16n8k8.row.col.f32.tf32.tf32.f32 "
        "{%0,%1,%2,%3}, {%4,%5,%6,%7}, {%8,%9}, {%0,%1,%2,%3};\n"
        : "+f"(c[0]), "+f"(c[1]), "+f"(c[2]), "+f"(c[3])
        : "r"(a[0]), "r"(a[1]), "r"(a[2]), "r"(a[3]), "r"(b0), "r"(b1));
}
__device__ __forceinline__ int pc8(int r) { return ((r & 3) << 1) | (r >> 2); }

__device__ __forceinline__ void cpa16(uint32_t dst, const void* src) {
    asm volatile("cp.async.cg.shared.global [%0], [%1], 16;" :: "r"(dst), "l"(src));
}
#define CP_COMMIT() asm volatile("cp.async.commit_group;")
#define CP_WAIT1()  asm volatile("cp.async.wait_group 1;")
#define CP_WAIT0()  asm volatile("cp.async.wait_group 0;")

// ---------------- K1a: mp_weight normalization + tf32/permute ----------------
__global__ void norm_kernel(const float* __restrict__ wq, const float* __restrict__ wp) {
    int r = blockIdx.x;
    bool is_q = (r < 3 * CDIM);
    const float* src = is_q ? wq + (size_t)r * CDIM : wp + (size_t)(r - 3 * CDIM) * CDIM;
    float* dst = is_q ? g_wqkv_n + (size_t)r * CDIM : g_wproj_n + (size_t)(r - 3 * CDIM) * CDIM;

    float4 v = reinterpret_cast<const float4*>(src)[threadIdx.x];
    float ss = v.x * v.x + v.y * v.y + v.z * v.z + v.w * v.w;
    for (int o = 16; o; o >>= 1) ss += __shfl_xor_sync(0xffffffffu, ss, o);
    __shared__ float wsum[4];
    if ((threadIdx.x & 31) == 0) wsum[threadIdx.x >> 5] = ss;
    __syncthreads();
    float nrm = sqrtf(wsum[0] + wsum[1] + wsum[2] + wsum[3]);
    float s512 = sqrtf((float)CDIM);
    float scale = 1.0f / ((1e-4f + nrm / s512) * s512);
    float o4[4] = {v.x * scale, v.y * scale, v.z * scale, v.w * scale};
    int c0 = threadIdx.x * 4;
#pragma unroll
    for (int j = 0; j < 4; j++) {
        int c = c0 + j;
        dst[(c & ~7) | pc8(c & 7)] = __uint_as_float(f2tf(o4[j]));
    }
}

// ---------------- K1b: rope table ----------------
__global__ void rope_table_kernel() {
    int idx = blockIdx.x * blockDim.x + threadIdx.x;
    if (idx < 64 * 32) {
        int t = idx >> 5, j = idx & 31;
        float inv = powf(10000.0f, -(2.0f * (float)j) / 64.0f);
        float a = (float)t * inv;
        g_rope[idx] = make_float2(cosf(a), sinf(a));
    }
}

// ---------------- K1c: 512x256 transpose -> [b][s][k_phys] tf32 ----------------
__global__ void tr_kernel(const float* __restrict__ src, float* __restrict__ dst) {
    __shared__ float t[32][33];
    int bb = blockIdx.z;
    int k0 = blockIdx.x * 32, s0 = blockIdx.y * 32;
    int tx = threadIdx.x, ty = threadIdx.y;
#pragma unroll
    for (int j = 0; j < 4; j++)
        t[ty + j * 8][tx] = src[((size_t)bb * CDIM + (k0 + ty + j * 8)) * HW + s0 + tx];
    __syncthreads();
    int kp = k0 + ((tx & ~7) | pc8(tx & 7));
#pragma unroll
    for (int j = 0; j < 4; j++)
        dst[((size_t)bb * HW + s0 + ty + j * 8) * CDIM + kp] =
            __uint_as_float(f2tf(t[tx][ty + j * 8]));
}

// ---------------- K2: QKV GEMM (tf32 mma) -> q/k/v [b][head][s][ch] ----------------
#define QS 20
__global__ __launch_bounds__(128) void qkv_gemm_kernel() {
    __shared__ float As[2][64 * QS];
    __shared__ float Bs[2][64 * QS];
    int sblk = blockIdx.x, oblk = blockIdx.y, bb = blockIdx.z;
    int tid = threadIdx.x;
    int w = tid >> 5, l = tid & 31;
    int la = l >> 2, lb = l & 3;

    const float* xa = g_xt + ((size_t)bb * HW + sblk * 64) * CDIM;
    const float* wb = g_wqkv_n + (size_t)oblk * 64 * CDIM;

    int row = tid >> 1, half = tid & 1;
    uint32_t as_u[2] = {(uint32_t)__cvta_generic_to_shared(As[0]),
                        (uint32_t)__cvta_generic_to_shared(As[1])};
    uint32_t bs_u[2] = {(uint32_t)__cvta_generic_to_shared(Bs[0]),
                        (uint32_t)__cvta_generic_to_shared(Bs[1])};

    auto load_stage = [&](int kc) {
        int st = kc & 1;
        uint32_t ad = as_u[st] + (uint32_t)(row * QS + half * 8) * 4u;
        uint32_t bd = bs_u[st] + (uint32_t)(row * QS + half * 8) * 4u;
        const float* asrc = xa + (size_t)row * CDIM + kc * 16 + half * 8;
        const float* bsrc = wb + (size_t)row * CDIM + kc * 16 + half * 8;
        cpa16(ad, asrc); cpa16(ad + 16, asrc + 4);
        cpa16(bd, bsrc); cpa16(bd + 16, bsrc + 4);
    };

    float acc[8][4] = {};
    load_stage(0); CP_COMMIT();

    for (int kc = 0; kc < 32; kc++) {
        if (kc + 1 < 32) { load_stage(kc + 1); CP_COMMIT(); CP_WAIT1(); }
        else CP_WAIT0();
        __syncthreads();
        const float* Ab = As[kc & 1];
        const float* Bb = Bs[kc & 1];
#pragma unroll
        for (int c2 = 0; c2 < 2; c2++) {
            uint2 a0 = *reinterpret_cast<const uint2*>(&Ab[(w * 16 + la) * QS + c2 * 8 + 2 * lb]);
            uint2 a1 = *reinterpret_cast<const uint2*>(&Ab[(w * 16 + la + 8) * QS + c2 * 8 + 2 * lb]);
            unsigned A[4] = {a0.x, a1.x, a0.y, a1.y};
#pragma unroll
            for (int nn = 0; nn < 8; nn++) {
                uint2 b = *reinterpret_cast<const uint2*>(&Bb[(nn * 8 + la) * QS + c2 * 8 + 2 * lb]);
                mma8(acc[nn], A, b.x, b.y);
            }
        }
        __syncthreads();
    }

    int which = oblk >> 3;
    int head = oblk & 7;
    float* dst = ((which == 0) ? g_q : (which == 1) ? g_k : g_v) +
                 (size_t)(bb * NH + head) * HW * CH;
    int srow = sblk * 64 + w * 16 + la;
#pragma unroll
    for (int nn = 0; nn < 8; nn++) {
        int ch = nn * 8 + 2 * lb;
        *reinterpret_cast<float2*>(&dst[(size_t)srow * CH + ch]) =
            make_float2(acc[nn][0], acc[nn][1]);
        *reinterpret_cast<float2*>(&dst[(size_t)(srow + 8) * CH + ch]) =
            make_float2(acc[nn][2], acc[nn][3]);
    }
}

// ---------------- K3: flash attention v8 ----------------
// 128 thr, 2 q-tiles/warp, 4-way KV split. 3-stage K + 3-stage RAW V,
// single barrier/iter, V fed to mma directly (HW tf32 truncation).
__global__ __launch_bounds__(128, 2) void attn_kernel(const float* __restrict__ ck,
                                                      const float* __restrict__ cv) {
    extern __shared__ float smf[];
    // K stages: s*64*SK (s=0..2); V stages: (3+s)*64*SK
    int qp = blockIdx.x >> 2, kvq = blockIdx.x & 3;
    int head = blockIdx.y, bb = blockIdx.z;
    int bhi = bb * NH + head;
    int tid = threadIdx.x;
    int w = tid >> 5, l = tid & 31;
    int la = l >> 2, lb = l & 3;

    uint32_t sm_u = (uint32_t)__cvta_generic_to_shared(smf);
    int krow = tid >> 1, half = tid & 1;
    int krow_p = (krow & ~7) | pc8(krow & 7);

    auto src_ptr = [&](const float* cache, const float* cur, int i) -> const float* {
        int ktg = kvq * ITERS + i;
        int t = ktg >> 2, st = ktg & 3;
        if (t < TCACHE)
            return cache + ((((size_t)bhi * TCACHE + t) * HW + st * 64)) * CH;
        return cur + (((size_t)bhi * HW + st * 64)) * CH;
    };

    auto issue = [&](int i) {
        int s = i % 3;
        const float* kp = src_ptr(ck, g_k, i);
        uint32_t kd = sm_u + (uint32_t)(s * 64 * SK + krow_p * SK + half * 32) * 4u;
        const float* ks = kp + krow * CH + half * 32;
#pragma unroll
        for (int c = 0; c < 8; c++) cpa16(kd + c * 16, ks + c * 4);
        const float* vp = src_ptr(cv, g_v, i);
        uint32_t vd = sm_u + (uint32_t)((3 + s) * 64 * SK + krow * SK + half * 32) * 4u;
        const float* vs = vp + krow * CH + half * 32;
#pragma unroll
        for (int c = 0; c < 8; c++) cpa16(vd + c * 16, vs + c * 4);
    };

    // ---- prologue: stage Q (rope 63, * log2e/8, tf32, ch-permuted) ----
    {
        int r = tid;
        const float* qpv = g_q + (((size_t)bhi) * HW + qp * 128 + r) * CH;
        const float2* tq = g_rope + 63 * 32;
        const float sc = 0.125f * LOG2E;
        unsigned* pr = reinterpret_cast<unsigned*>(smf + r * SK);
#pragma unroll
        for (int g = 0; g < 8; g++) {
            float4 x0 = *reinterpret_cast<const float4*>(qpv + 8 * g);
            float4 x1 = *reinterpret_cast<const float4*>(qpv + 8 * g + 4);
            float2 t0 = tq[4 * g], t1 = tq[4 * g + 1], t2 = tq[4 * g + 2], t3 = tq[4 * g + 3];
            float l0 = (x0.x * t0.x - x0.y * t0.y) * sc;
            float l1 = (x0.x * t0.y + x0.y * t0.x) * sc;
            float l2 = (x0.z * t1.x - x0.w * t1.y) * sc;
            float l3 = (x0.z * t1.y + x0.w * t1.x) * sc;
            float l4 = (x1.x * t2.x - x1.y * t2.y) * sc;
            float l5 = (x1.x * t2.y + x1.y * t2.x) * sc;
            float l6 = (x1.z * t3.x - x1.w * t3.y) * sc;
            float l7 = (x1.z * t3.y + x1.w * t3.x) * sc;
            pr[8 * g + 0] = f2tf(l0); pr[8 * g + 1] = f2tf(l4);
            pr[8 * g + 2] = f2tf(l1); pr[8 * g + 3] = f2tf(l5);
            pr[8 * g + 4] = f2tf(l2); pr[8 * g + 5] = f2tf(l6);
            pr[8 * g + 6] = f2tf(l3); pr[8 * g + 7] = f2tf(l7);
        }
    }
    __syncthreads();

    unsigned qa[2][8][4];
#pragma unroll
    for (int tt = 0; tt < 2; tt++) {
        int r0 = tt * 64 + 16 * w + la;
#pragma unroll
        for (int kk = 0; kk < 8; kk++) {
            uint2 p0 = *reinterpret_cast<const uint2*>(&smf[r0 * SK + kk * 8 + 2 * lb]);
            uint2 p1 = *reinterpret_cast<const uint2*>(&smf[(r0 + 8) * SK + kk * 8 + 2 * lb]);
            qa[tt][kk][0] = p0.x; qa[tt][kk][1] = p1.x; qa[tt][kk][2] = p0.y; qa[tt][kk][3] = p1.y;
        }
    }
    __syncthreads();

    issue(0); CP_COMMIT();
    issue(1); CP_COMMIT();

    float oacc[2][8][4] = {};
    float ls[2][2] = {};

    for (int i = 0; i < ITERS; i++) {
        int s = i % 3;
        CP_WAIT1();   // group i landed (own view)

        // ---- convert own K rows: rope + tf32 + ch-permute, in place ----
        {
            int t = (kvq * ITERS + i) >> 2;
            float* kb = smf + s * 64 * SK + krow_p * SK;
            const float2* tt_ = g_rope + t * 32 + half * 16;
#pragma unroll
            for (int g2 = 0; g2 < 4; g2++) {
                int ch0 = (half * 4 + g2) * 8;
                float4 a = *reinterpret_cast<const float4*>(kb + ch0);
                float4 b = *reinterpret_cast<const float4*>(kb + ch0 + 4);
                float2 t0 = tt_[4 * g2], t1 = tt_[4 * g2 + 1], t2 = tt_[4 * g2 + 2], t3 = tt_[4 * g2 + 3];
                float l0 = a.x * t0.x - a.y * t0.y;
                float l1 = a.x * t0.y + a.y * t0.x;
                float l2 = a.z * t1.x - a.w * t1.y;
                float l3 = a.z * t1.y + a.w * t1.x;
                float l4 = b.x * t2.x - b.y * t2.y;
                float l5 = b.x * t2.y + b.y * t2.x;
                float l6 = b.z * t3.x - b.w * t3.y;
                float l7 = b.z * t3.y + b.w * t3.x;
                uint4 o0 = make_uint4(f2tf(l0), f2tf(l4), f2tf(l1), f2tf(l5));
                uint4 o1 = make_uint4(f2tf(l2), f2tf(l6), f2tf(l3), f2tf(l7));
                *reinterpret_cast<uint4*>(kb + ch0)     = o0;
                *reinterpret_cast<uint4*>(kb + ch0 + 4) = o1;
            }
        }
        __syncthreads();   // publish K/V tile i; seal stage (i+2)%3 reads (iter i-1)
        if (i + 2 < ITERS) issue(i + 2);
        CP_COMMIT();       // unconditional: keeps group numbering aligned

        const float* Kb = smf + s * 64 * SK;
        const float* Vb = smf + (3 + s) * 64 * SK;

        // ---- S = QK^T (hoisted K frags), P = exp2 into pa ----
        unsigned pa[2][8][4];
        float s00 = 0.f, s01 = 0.f, s10 = 0.f, s11 = 0.f;
#pragma unroll
        for (int nn = 0; nn < 8; nn++) {
            const float* kr = Kb + (nn * 8 + la) * SK;
            uint2 bf[8];
#pragma unroll
            for (int kk = 0; kk < 8; kk++)
                bf[kk] = *reinterpret_cast<const uint2*>(kr + kk * 8 + 2 * lb);
#pragma unroll
            for (int tt = 0; tt < 2; tt++) {
                float c[4] = {0.f, 0.f, 0.f, 0.f};
#pragma unroll
                for (int kk = 0; kk < 8; kk++) mma8(c, qa[tt][kk], bf[kk].x, bf[kk].y);
                float p0 = ex2(c[0]);
                float p1 = ex2(c[1]);
                float p2 = ex2(c[2]);
                float p3 = ex2(c[3]);
                if (tt == 0) { s00 += p0 + p1; s01 += p2 + p3; }
                else         { s10 += p0 + p1; s11 += p2 + p3; }
                pa[tt][nn][0] = __float_as_uint(p0);
                pa[tt][nn][1] = __float_as_uint(p2);
                pa[tt][nn][2] = __float_as_uint(p1);
                pa[tt][nn][3] = __float_as_uint(p3);
            }
        }
        s00 += __shfl_xor_sync(0xffffffffu, s00, 1);
        s00 += __shfl_xor_sync(0xffffffffu, s00, 2);
        s01 += __shfl_xor_sync(0xffffffffu, s01, 1);
        s01 += __shfl_xor_sync(0xffffffffu, s01, 2);
        s10 += __shfl_xor_sync(0xffffffffu, s10, 1);
        s10 += __shfl_xor_sync(0xffffffffu, s10, 2);
        s11 += __shfl_xor_sync(0xffffffffu, s11, 1);
        s11 += __shfl_xor_sync(0xffffffffu, s11, 2);
        ls[0][0] += s00; ls[0][1] += s01;
        ls[1][0] += s10; ls[1][1] += s11;

        // ---- O += P V, B read directly from raw V tile (HW truncates to tf32) ----
#pragma unroll
        for (int kk = 0; kk < 8; kk++) {
            const float* vr0 = Vb + (kk * 8 + lb) * SK + la;
            const float* vr1 = vr0 + 4 * SK;
#pragma unroll
            for (int nn = 0; nn < 8; nn++) {
                unsigned b0 = __float_as_uint(vr0[nn * 8]);
                unsigned b1 = __float_as_uint(vr1[nn * 8]);
                mma8(oacc[0][nn], pa[0][kk], b0, b1);
                mma8(oacc[1][nn], pa[1][kk], b0, b1);
            }
        }
    }

    // ---- epilogue ----
    int pbase = ((bhi * 2 + qp) * NKV + kvq);
    float* po = g_po + (size_t)pbase * 8192;
    int prow = 16 * w + la;
#pragma unroll
    for (int tt = 0; tt < 2; tt++) {
        int row = tt * 64 + prow;
#pragma unroll
        for (int nn = 0; nn < 8; nn++) {
            int ch = nn * 8 + 2 * lb;
            po[(ch + 0) * 128 + row]     = oacc[tt][nn][0];
            po[(ch + 1) * 128 + row]     = oacc[tt][nn][1];
            po[(ch + 0) * 128 + row + 8] = oacc[tt][nn][2];
            po[(ch + 1) * 128 + row + 8] = oacc[tt][nn][3];
        }
        if (lb == 0) {
            g_pl[pbase * 128 + row]     = ls[tt][0];
            g_pl[pbase * 128 + row + 8] = ls[tt][1];
        }
    }
}

// ---------------- K3b: split-KV combine -> g_o ----------------
__global__ __launch_bounds__(256) void combine_kernel() {
    int qp = blockIdx.x, head = blockIdx.y, bb = blockIdx.z;
    int pb = (((bb * NH + head) * 2 + qp) * NKV);
    int tid = threadIdx.x;
    __shared__ float il[128];
    if (tid < 128) {
        float den = 0.f;
#pragma unroll
        for (int k = 0; k < NKV; k++) den += g_pl[(pb + k) * 128 + tid];
        il[tid] = 1.0f / den;
    }
    __syncthreads();
    int ch = tid >> 2, sg = tid & 3;
    float* dst = g_o + ((size_t)bb * CDIM + (ch * NH + head)) * HW + qp * 128;
#pragma unroll 4
    for (int rr = 0; rr < 32; rr++) {
        int r = sg * 32 + rr;
        float acc = 0.f;
#pragma unroll
        for (int k = 0; k < NKV; k++)
            acc += g_po[(size_t)(pb + k) * 8192 + ch * 128 + r];
        dst[r] = acc * il[r];
    }
}

// ---------------- K4: proj GEMM (tf32 mma) + mp_sum ----------------
__global__ __launch_bounds__(128) void proj_kernel(const float* __restrict__ x,
                                                   float* __restrict__ out) {
    __shared__ float As[2][64 * QS];
    __shared__ float Bs[2][64 * QS];
    int sblk = blockIdx.x, oblk = blockIdx.y, bb = blockIdx.z;
    int tid = threadIdx.x;
    int w = tid >> 5, l = tid & 31;
    int la = l >> 2, lb = l & 3;

    const float* xa = g_ot + ((size_t)bb * HW + sblk * 64) * CDIM;
    const float* wb = g_wproj_n + (size_t)oblk * 64 * CDIM;

    int row = tid >> 1, half = tid & 1;
    uint32_t as_u[2] = {(uint32_t)__cvta_generic_to_shared(As[0]),
                        (uint32_t)__cvta_generic_to_shared(As[1])};
    uint32_t bs_u[2] = {(uint32_t)__cvta_generic_to_shared(Bs[0]),
                        (uint32_t)__cvta_generic_to_shared(Bs[1])};

    auto load_stage = [&](int kc) {
        int st = kc & 1;
        uint32_t ad = as_u[st] + (uint32_t)(row * QS + half * 8) * 4u;
        uint32_t bd = bs_u[st] + (uint32_t)(row * QS + half * 8) * 4u;
        const float* asrc = xa + (size_t)row * CDIM + kc * 16 + half * 8;
        const float* bsrc = wb + (size_t)row * CDIM + kc * 16 + half * 8;
        cpa16(ad, asrc); cpa16(ad + 16, asrc + 4);
        cpa16(bd, bsrc); cpa16(bd + 16, bsrc + 4);
    };

    float acc[8][4] = {};
    load_stage(0); CP_COMMIT();

    for (int kc = 0; kc < 32; kc++) {
        if (kc + 1 < 32) { load_stage(kc + 1); CP_COMMIT(); CP_WAIT1(); }
        else CP_WAIT0();
        __syncthreads();
        const float* Ab = As[kc & 1];
        const float* Bb = Bs[kc & 1];
#pragma unroll
        for (int c2 = 0; c2 < 2; c2++) {
            uint2 a0 = *reinterpret_cast<const uint2*>(&Ab[(w * 16 + la) * QS + c2 * 8 + 2 * lb]);
            uint2 a1 = *reinterpret_cast<const uint2*>(&Ab[(w * 16 + la + 8) * QS + c2 * 8 + 2 * lb]);
            unsigned A[4] = {a0.x, a1.x, a0.y, a1.y};
#pragma unroll
            for (int nn = 0; nn < 8; nn++) {
                uint2 b = *reinterpret_cast<const uint2*>(&Bb[(nn * 8 + la) * QS + c2 * 8 + 2 * lb]);
                mma8(acc[nn], A, b.x, b.y);
            }
        }
        __syncthreads();
    }

    const float norm = 1.3130643286f;  // 1/sqrt(0.7^2+0.3^2)
    int srow = sblk * 64 + w * 16 + la;
#pragma unroll
    for (int nn = 0; nn < 8; nn++) {
        int oc = oblk * 64 + nn * 8 + 2 * lb;
        size_t i00 = ((size_t)bb * CDIM + oc) * HW;
        size_t i01 = ((size_t)bb * CDIM + oc + 1) * HW;
        out[i00 + srow]     = (0.7f * x[i00 + srow]     + 0.3f * acc[nn][0]) * norm;
        out[i01 + srow]     = (0.7f * x[i01 + srow]     + 0.3f * acc[nn][1]) * norm;
        out[i00 + srow + 8] = (0.7f * x[i00 + srow + 8] + 0.3f * acc[nn][2]) * norm;
        out[i01 + srow + 8] = (0.7f * x[i01 + srow + 8] + 0.3f * acc[nn][3]) * norm;
    }
}

extern "C" void kernel_launch(void* const* d_in, const int* in_sizes, int n_in,
                              void* d_out, int out_size) {
    const float* x     = (const float*)d_in[0];
    const float* ck    = (const float*)d_in[1];
    const float* cv    = (const float*)d_in[2];
    const float* wqkv  = (const float*)d_in[3];
    const float* wproj = (const float*)d_in[4];
    float* out = (float*)d_out;

    norm_kernel<<<4 * CDIM, 128>>>(wqkv, wproj);
    rope_table_kernel<<<8, 256>>>();

    float* xt_sym; cudaGetSymbolAddress((void**)&xt_sym, g_xt);
    float* ot_sym; cudaGetSymbolAddress((void**)&ot_sym, g_ot);
    float* o_sym;  cudaGetSymbolAddress((void**)&o_sym,  g_o);

    tr_kernel<<<dim3(16, 8, 4), dim3(32, 8)>>>(x, xt_sym);
    qkv_gemm_kernel<<<dim3(4, 24, 4), 128>>>();

    int smem = 6 * 64 * SK * (int)sizeof(float);  // 110592 B -> 2 CTAs/SM
    cudaFuncSetAttribute(attn_kernel, cudaFuncAttributeMaxDynamicSharedMemorySize, smem);
    attn_kernel<<<dim3(8, NH, 4), 128, smem>>>(ck, cv);

    combine_kernel<<<dim3(2, NH, BATCH), 256>>>();
    tr_kernel<<<dim3(16, 8, 4), dim3(32, 8)>>>(o_sym, ot_sym);
    proj_kernel<<<dim3(4, 8, 4), 128>>>(x, out);
}